// round 3
// baseline (speedup 1.0000x reference)
#include <cuda_runtime.h>
#include <math.h>

// Problem constants
#define BB 16
#define TT 128
#define DD 8192           // C*H*W = 32*16*16
#define FF 16             // NUM_FEAT
#define GG 4096           // NUM_FEAT*H*W
#define MM (BB*TT)        // 2048 rows

// ---------------- scratch (device globals; no allocs allowed) ----------------
__device__ float g_q[MM * FF];
__device__ float g_k[MM * FF];
__device__ float g_attn[BB * TT * TT];     // attn[b][t][s]
__device__ float g_rs[MM];                 // rowsum_s attn[b][t][s]
__device__ float g_y[(size_t)MM * DD];     // y = attn @ x1   (64 MB)

// =============================================================================
// K1: q = x1 @ w1^T + b1 ; k = x2 @ w2^T + b2
// grid 128 blocks (16 rows each), 256 threads (r = tid>>4 in 0..15, f = tid&15)
// =============================================================================
__global__ __launch_bounds__(256) void k_qk(
    const float* __restrict__ x1, const float* __restrict__ x2,
    const float* __restrict__ w1, const float* __restrict__ b1,
    const float* __restrict__ w2, const float* __restrict__ b2)
{
    __shared__ float Xs1[16][132];
    __shared__ float Xs2[16][132];
    __shared__ float Ws1[16][132];
    __shared__ float Ws2[16][132];

    const int tid  = threadIdx.x;
    const int r    = tid >> 4;
    const int f    = tid & 15;
    const int row0 = blockIdx.x * 16;

    float accq = 0.f, acck = 0.f;

    for (int kc = 0; kc < DD; kc += 128) {
        #pragma unroll
        for (int i = 0; i < 2; ++i) {
            int lin = tid + i * 256;            // float4 unit, 0..511
            int row = lin >> 5;                 // 0..15
            int col = (lin & 31) << 2;          // 0..124
            *(float4*)&Xs1[row][col] = *(const float4*)&x1[(size_t)(row0 + row) * DD + kc + col];
            *(float4*)&Xs2[row][col] = *(const float4*)&x2[(size_t)(row0 + row) * DD + kc + col];
            *(float4*)&Ws1[row][col] = *(const float4*)&w1[(size_t)row * DD + kc + col];
            *(float4*)&Ws2[row][col] = *(const float4*)&w2[(size_t)row * DD + kc + col];
        }
        __syncthreads();
        #pragma unroll 8
        for (int kk = 0; kk < 128; ++kk) {
            accq += Xs1[r][kk] * Ws1[f][kk];
            acck += Xs2[r][kk] * Ws2[f][kk];
        }
        __syncthreads();
    }
    g_q[(row0 + r) * FF + f] = accq + b1[f];
    g_k[(row0 + r) * FF + f] = acck + b2[f];
}

// =============================================================================
// K2: scores[b,t,s] = sum_f q[b,t,f] k[b,s,f]; softmax over t (axis=1);
//     also rowsum rs[b,t] = sum_s attn[b,t,s].
// grid = B (16), block = 128 threads (thread = column s). Scores are
// recomputed (2 passes) — cheaper than staging 64 KB in smem.
// =============================================================================
__global__ __launch_bounds__(128) void k_scores_softmax()
{
    __shared__ float qs[TT][17];
    __shared__ float red[4];

    const int b = blockIdx.x;
    const int s = threadIdx.x;
    const int lane = s & 31, wid = s >> 5;

    // stage q[b,:,:] in smem
    #pragma unroll
    for (int i = 0; i < 16; ++i) {
        int lin = s + i * 128;
        int t = lin >> 4, f = lin & 15;
        qs[t][f] = g_q[(b * TT + t) * FF + f];
    }
    float kr[FF];
    #pragma unroll
    for (int j = 0; j < FF; ++j) kr[j] = g_k[(b * TT + s) * FF + j];
    __syncthreads();

    // pass 1: online max/sum over t for this column s
    float m = -1e30f, l = 0.f;
    for (int t = 0; t < TT; ++t) {
        float sc = 0.f;
        #pragma unroll
        for (int j = 0; j < FF; ++j) sc += qs[t][j] * kr[j];
        float nm = fmaxf(m, sc);
        l = l * expf(m - nm) + expf(sc - nm);
        m = nm;
    }
    float inv = 1.f / l;

    // pass 2: write attn, and block-reduce each row's sum over s
    for (int t = 0; t < TT; ++t) {
        float sc = 0.f;
        #pragma unroll
        for (int j = 0; j < FF; ++j) sc += qs[t][j] * kr[j];
        float a = expf(sc - m) * inv;
        g_attn[(b * TT + t) * TT + s] = a;

        float v = a;
        #pragma unroll
        for (int off = 16; off > 0; off >>= 1)
            v += __shfl_down_sync(0xffffffffu, v, off);
        if (lane == 0) red[wid] = v;
        __syncthreads();
        if (s == 0) g_rs[b * TT + t] = red[0] + red[1] + red[2] + red[3];
        __syncthreads();
    }
}

// =============================================================================
// K3: y[b,t,d] = sum_s attn[b,t,s] * x1[b,s,d]
// grid (d-tiles=16, t-tiles=2, b=16), block 512 (one d-column per thread),
// 64 t-accumulators per thread; attn tile transposed in smem for float4 reads.
// =============================================================================
__global__ __launch_bounds__(512) void k_y(const float* __restrict__ x1)
{
    __shared__ float AsT[TT][68];   // [s][t], stride 68 (16B-aligned rows)

    const int tid = threadIdx.x;
    const int b   = blockIdx.z;
    const int t0  = blockIdx.y * 64;
    const int col = blockIdx.x * 512 + tid;

    #pragma unroll
    for (int i = 0; i < 16; ++i) {
        int lin = tid + i * 512;
        int s = lin & 127, t = lin >> 7;
        AsT[s][t] = g_attn[(b * TT + t0 + t) * TT + s];
    }
    __syncthreads();

    float acc[64];
    #pragma unroll
    for (int t = 0; t < 64; ++t) acc[t] = 0.f;

    for (int s = 0; s < TT; ++s) {
        float xv = x1[(size_t)(b * TT + s) * DD + col];
        const float4* ar = (const float4*)&AsT[s][0];
        #pragma unroll
        for (int q4 = 0; q4 < 16; ++q4) {
            float4 a = ar[q4];
            acc[q4 * 4 + 0] += a.x * xv;
            acc[q4 * 4 + 1] += a.y * xv;
            acc[q4 * 4 + 2] += a.z * xv;
            acc[q4 * 4 + 3] += a.w * xv;
        }
    }
    #pragma unroll
    for (int t = 0; t < 64; ++t)
        g_y[(size_t)(b * TT + t0 + t) * DD + col] = acc[t];
}

// =============================================================================
// K4: out[m, g] = sum_k y[m,k] * w3[g,k] + rs[m] * b3[g]
// Classic TN SGEMM: 128x128 block tile, BK=16, 256 threads, 8x8 micro-tile.
// =============================================================================
__global__ __launch_bounds__(256, 2) void k_out(
    const float* __restrict__ w3, const float* __restrict__ b3,
    float* __restrict__ out)
{
    __shared__ float As[16][132];
    __shared__ float Bs[16][132];

    const int tid = threadIdx.x;
    const int tx  = tid & 15;       // n micro
    const int ty  = tid >> 4;       // m micro
    const int col0 = blockIdx.x * 128;
    const int row0 = blockIdx.y * 128;

    float acc[8][8];
    #pragma unroll
    for (int i = 0; i < 8; ++i)
        #pragma unroll
        for (int j = 0; j < 8; ++j) acc[i][j] = 0.f;

    for (int kb = 0; kb < DD; kb += 16) {
        #pragma unroll
        for (int i = 0; i < 2; ++i) {
            int lin  = tid + i * 256;           // float4 unit, 0..511
            int arow = lin >> 2;                // 0..127
            int k4   = (lin & 3) << 2;          // 0,4,8,12
            float4 va = *(const float4*)&g_y[(size_t)(row0 + arow) * DD + kb + k4];
            As[k4 + 0][arow] = va.x; As[k4 + 1][arow] = va.y;
            As[k4 + 2][arow] = va.z; As[k4 + 3][arow] = va.w;
            float4 vb = *(const float4*)&w3[(size_t)(col0 + arow) * DD + kb + k4];
            Bs[k4 + 0][arow] = vb.x; Bs[k4 + 1][arow] = vb.y;
            Bs[k4 + 2][arow] = vb.z; Bs[k4 + 3][arow] = vb.w;
        }
        __syncthreads();

        #pragma unroll
        for (int k = 0; k < 16; ++k) {
            float4 a0 = *(const float4*)&As[k][ty * 8];
            float4 a1 = *(const float4*)&As[k][ty * 8 + 4];
            float4 b0 = *(const float4*)&Bs[k][tx * 8];
            float4 b1 = *(const float4*)&Bs[k][tx * 8 + 4];
            float av[8] = {a0.x, a0.y, a0.z, a0.w, a1.x, a1.y, a1.z, a1.w};
            float bv[8] = {b0.x, b0.y, b0.z, b0.w, b1.x, b1.y, b1.z, b1.w};
            #pragma unroll
            for (int i = 0; i < 8; ++i)
                #pragma unroll
                for (int j = 0; j < 8; ++j)
                    acc[i][j] += av[i] * bv[j];
        }
        __syncthreads();
    }

    float rsv[8], b3v[8];
    #pragma unroll
    for (int i = 0; i < 8; ++i) rsv[i] = g_rs[row0 + ty * 8 + i];
    #pragma unroll
    for (int j = 0; j < 8; ++j) b3v[j] = b3[col0 + tx * 8 + j];

    #pragma unroll
    for (int i = 0; i < 8; ++i) {
        int m = row0 + ty * 8 + i;
        #pragma unroll
        for (int j = 0; j < 8; ++j)
            out[(size_t)m * GG + col0 + tx * 8 + j] = acc[i][j] + rsv[i] * b3v[j];
    }
}

// =============================================================================
extern "C" void kernel_launch(void* const* d_in, const int* in_sizes, int n_in,
                              void* d_out, int out_size)
{
    const float* x1 = (const float*)d_in[0];
    const float* x2 = (const float*)d_in[1];
    const float* w1 = (const float*)d_in[2];
    const float* b1 = (const float*)d_in[3];
    const float* w2 = (const float*)d_in[4];
    const float* b2 = (const float*)d_in[5];
    const float* w3 = (const float*)d_in[6];
    const float* b3 = (const float*)d_in[7];
    float* out = (float*)d_out;

    k_qk<<<MM / 16, 256>>>(x1, x2, w1, b1, w2, b2);
    k_scores_softmax<<<BB, 128>>>();
    k_y<<<dim3(DD / 512, TT / 64, BB), 512>>>(x1);
    k_out<<<dim3(GG / 128, MM / 128), 256>>>(w3, b3, out);
}

// round 5
// speedup vs baseline: 1.7023x; 1.7023x over previous
#include <cuda_runtime.h>
#include <cuda_bf16.h>
#include <stdint.h>
#include <math.h>

// Problem constants
#define BB 16
#define TT 128
#define DD 8192           // C*H*W
#define FF 16             // NUM_FEAT
#define GG 4096           // NUM_FEAT*H*W
#define MM (BB*TT)        // 2048 rows

// ---------------- scratch (device globals; no allocs allowed) ----------------
__device__ float g_q[MM * FF];
__device__ float g_k[MM * FF];
__device__ float g_attn[BB * TT * TT];
__device__ float g_rs[MM];
__device__ __nv_bfloat16 g_yhi[(size_t)MM * DD];   // 32 MB, row-major [m][k]
__device__ __nv_bfloat16 g_ylo[(size_t)MM * DD];   // 32 MB
__device__ __nv_bfloat16 g_w3hi[(size_t)GG * DD];  // 64 MB, row-major [n][k]
__device__ __nv_bfloat16 g_w3lo[(size_t)GG * DD];  // 64 MB

// ======================= PTX helpers (compute_103-safe) ======================
__device__ __forceinline__ uint32_t smem_u32(const void* p) {
    uint32_t a;
    asm("{ .reg .u64 t; cvta.to.shared.u64 t, %1; cvt.u32.u64 %0, t; }" : "=r"(a) : "l"(p));
    return a;
}
__device__ __forceinline__ void cp_async16(uint32_t dst, const void* src) {
    asm volatile("cp.async.cg.shared.global [%0], [%1], 16;" :: "r"(dst), "l"(src) : "memory");
}
#define CP_COMMIT() asm volatile("cp.async.commit_group;" ::: "memory")
#define CP_WAIT1()  asm volatile("cp.async.wait_group 1;" ::: "memory")

__device__ __forceinline__ void ldsm4(uint32_t* r, uint32_t addr) {
    asm volatile("ldmatrix.sync.aligned.m8n8.x4.shared.b16 {%0,%1,%2,%3}, [%4];"
        : "=r"(r[0]), "=r"(r[1]), "=r"(r[2]), "=r"(r[3]) : "r"(addr));
}
__device__ __forceinline__ void mma16816(float* d, const uint32_t* a, uint32_t b0, uint32_t b1) {
    asm volatile("mma.sync.aligned.m16n8k16.row.col.f32.bf16.bf16.f32 "
        "{%0,%1,%2,%3}, {%4,%5,%6,%7}, {%8,%9}, {%0,%1,%2,%3};"
        : "+f"(d[0]), "+f"(d[1]), "+f"(d[2]), "+f"(d[3])
        : "r"(a[0]), "r"(a[1]), "r"(a[2]), "r"(a[3]), "r"(b0), "r"(b1));
}

// =============================================================================
// K1: q = x1 @ w1^T + b1 ; k = x2 @ w2^T + b2
// =============================================================================
__global__ __launch_bounds__(256) void k_qk(
    const float* __restrict__ x1, const float* __restrict__ x2,
    const float* __restrict__ w1, const float* __restrict__ b1,
    const float* __restrict__ w2, const float* __restrict__ b2)
{
    __shared__ float Xs1[16][132];
    __shared__ float Xs2[16][132];
    __shared__ float Ws1[16][132];
    __shared__ float Ws2[16][132];

    const int tid  = threadIdx.x;
    const int r    = tid >> 4;
    const int f    = tid & 15;
    const int row0 = blockIdx.x * 16;

    float accq = 0.f, acck = 0.f;
    for (int kc = 0; kc < DD; kc += 128) {
        #pragma unroll
        for (int i = 0; i < 2; ++i) {
            int lin = tid + i * 256;
            int row = lin >> 5;
            int col = (lin & 31) << 2;
            *(float4*)&Xs1[row][col] = *(const float4*)&x1[(size_t)(row0 + row) * DD + kc + col];
            *(float4*)&Xs2[row][col] = *(const float4*)&x2[(size_t)(row0 + row) * DD + kc + col];
            *(float4*)&Ws1[row][col] = *(const float4*)&w1[(size_t)row * DD + kc + col];
            *(float4*)&Ws2[row][col] = *(const float4*)&w2[(size_t)row * DD + kc + col];
        }
        __syncthreads();
        #pragma unroll 8
        for (int kk = 0; kk < 128; ++kk) {
            accq += Xs1[r][kk] * Ws1[f][kk];
            acck += Xs2[r][kk] * Ws2[f][kk];
        }
        __syncthreads();
    }
    g_q[(row0 + r) * FF + f] = accq + b1[f];
    g_k[(row0 + r) * FF + f] = acck + b2[f];
}

// =============================================================================
// K2: scores + softmax over t (axis=1) + rowsums (no per-row block syncs)
// =============================================================================
__global__ __launch_bounds__(128) void k_scores_softmax()
{
    __shared__ float qs[TT][17];
    __shared__ float redp[4][TT];

    const int b = blockIdx.x;
    const int s = threadIdx.x;
    const int lane = s & 31, wid = s >> 5;

    #pragma unroll
    for (int i = 0; i < 16; ++i) {
        int lin = s + i * 128;
        int t = lin >> 4, f = lin & 15;
        qs[t][f] = g_q[(b * TT + t) * FF + f];
    }
    float kr[FF];
    #pragma unroll
    for (int j = 0; j < FF; ++j) kr[j] = g_k[(b * TT + s) * FF + j];
    __syncthreads();

    float m = -1e30f, l = 0.f;
    for (int t = 0; t < TT; ++t) {
        float sc = 0.f;
        #pragma unroll
        for (int j = 0; j < FF; ++j) sc += qs[t][j] * kr[j];
        float nm = fmaxf(m, sc);
        l = l * expf(m - nm) + expf(sc - nm);
        m = nm;
    }
    float inv = 1.f / l;

    for (int t = 0; t < TT; ++t) {
        float sc = 0.f;
        #pragma unroll
        for (int j = 0; j < FF; ++j) sc += qs[t][j] * kr[j];
        float a = expf(sc - m) * inv;
        g_attn[(b * TT + t) * TT + s] = a;

        float v = a;
        #pragma unroll
        for (int off = 16; off > 0; off >>= 1)
            v += __shfl_down_sync(0xffffffffu, v, off);
        if (lane == 0) redp[wid][t] = v;        // per-warp slot: no race, no sync
    }
    __syncthreads();
    if (s < TT)
        g_rs[b * TT + s] = redp[0][s] + redp[1][s] + redp[2][s] + redp[3][s];
}

// =============================================================================
// K3: y[b,t,d] = sum_s attn[b,t,s] * x1[b,s,d]  -> write bf16 hi/lo directly
// =============================================================================
__global__ __launch_bounds__(512) void k_y(const float* __restrict__ x1)
{
    __shared__ float AsT[TT][68];

    const int tid = threadIdx.x;
    const int b   = blockIdx.z;
    const int t0  = blockIdx.y * 64;
    const int col = blockIdx.x * 512 + tid;

    #pragma unroll
    for (int i = 0; i < 16; ++i) {
        int lin = tid + i * 512;
        int s = lin & 127, t = lin >> 7;
        AsT[s][t] = g_attn[(b * TT + t0 + t) * TT + s];
    }
    __syncthreads();

    float acc[64];
    #pragma unroll
    for (int t = 0; t < 64; ++t) acc[t] = 0.f;

    for (int s = 0; s < TT; ++s) {
        float xv = x1[(size_t)(b * TT + s) * DD + col];
        const float4* ar = (const float4*)&AsT[s][0];
        #pragma unroll
        for (int q4 = 0; q4 < 16; ++q4) {
            float4 a = ar[q4];
            acc[q4 * 4 + 0] += a.x * xv;
            acc[q4 * 4 + 1] += a.y * xv;
            acc[q4 * 4 + 2] += a.z * xv;
            acc[q4 * 4 + 3] += a.w * xv;
        }
    }
    #pragma unroll
    for (int t = 0; t < 64; ++t) {
        float v = acc[t];
        __nv_bfloat16 h = __float2bfloat16(v);
        __nv_bfloat16 lo = __float2bfloat16(v - __bfloat162float(h));
        size_t off = (size_t)(b * TT + t0 + t) * DD + col;
        g_yhi[off] = h;
        g_ylo[off] = lo;
    }
}

// =============================================================================
// K_split_w3: fp32 [G][D] -> bf16 hi/lo row-major (streaming)
// =============================================================================
__global__ __launch_bounds__(256) void k_split_w3(const float* __restrict__ src)
{
    size_t i4 = ((size_t)blockIdx.x * 256 + threadIdx.x);   // float4 index
    float4 v = *(const float4*)&src[i4 * 4];
    __nv_bfloat16 h0 = __float2bfloat16(v.x), h1 = __float2bfloat16(v.y);
    __nv_bfloat16 h2 = __float2bfloat16(v.z), h3 = __float2bfloat16(v.w);
    __nv_bfloat162 hp0; hp0.x = h0; hp0.y = h1;
    __nv_bfloat162 hp1; hp1.x = h2; hp1.y = h3;
    __nv_bfloat162 lp0, lp1;
    lp0.x = __float2bfloat16(v.x - __bfloat162float(h0));
    lp0.y = __float2bfloat16(v.y - __bfloat162float(h1));
    lp1.x = __float2bfloat16(v.z - __bfloat162float(h2));
    lp1.y = __float2bfloat16(v.w - __bfloat162float(h3));
    uint2 hu, lu;
    hu.x = *(uint32_t*)&hp0; hu.y = *(uint32_t*)&hp1;
    lu.x = *(uint32_t*)&lp0; lu.y = *(uint32_t*)&lp1;
    *(uint2*)&g_w3hi[i4 * 4] = hu;
    *(uint2*)&g_w3lo[i4 * 4] = lu;
}

// =============================================================================
// K4: out[m,g] = sum_k y[m,k] w3[g,k] + rs[m] b3[g]
// bf16 hi/lo 3-product HMMA GEMM. 256x256 tile, BK=32, 512 threads,
// 16 warps (4x4 grid of 64x64 warp tiles), 3-stage cp.async pipeline.
// Smem rows: 64B (32 bf16) with chunk swizzle c ^= (r>>1)&3 (ldsm conflict-free).
// =============================================================================
#define STAGE_BYTES 65536          // Ah(16K) Al(16K) Bh(16K) Bl(16K)
#define NSTG 3
#define SMEM_K4 (NSTG * STAGE_BYTES)

__global__ __launch_bounds__(512, 1) void k_out_tc(
    const float* __restrict__ b3, float* __restrict__ out)
{
    extern __shared__ char smem[];
    const uint32_t sb = smem_u32(smem);
    const int tid  = threadIdx.x;
    const int lane = tid & 31;
    const int wid  = tid >> 5;
    const int wm   = wid & 3;          // warp m index (0..3)
    const int wn   = wid >> 2;         // warp n index (0..3)
    const int rb   = blockIdx.x;       // M tile (0..7)
    const int nb   = blockIdx.y;       // N tile (0..15)

    const __nv_bfloat16* aH = g_yhi  + (size_t)rb * 256 * DD;
    const __nv_bfloat16* aL = g_ylo  + (size_t)rb * 256 * DD;
    const __nv_bfloat16* bH = g_w3hi + (size_t)nb * 256 * DD;
    const __nv_bfloat16* bL = g_w3lo + (size_t)nb * 256 * DD;

    // ---- loader: 8 x 16B chunks per thread per stage ----
    // id = i*512+tid; arr = i>>1 (0=Ah 1=Al 2=Bh 3=Bl); w = (i&1)*512+tid;
    // r = w>>2 (0..255 when combined over i parity? no: w in 0..1023, r=w>>2 0..255), c = w&3
    auto issue_stage = [&](int kt, int stage) {
        const uint32_t sbase = sb + stage * STAGE_BYTES;
        #pragma unroll
        for (int i = 0; i < 8; ++i) {
            const int arr = i >> 1;
            const int w   = ((i & 1) << 9) + tid;   // 0..1023
            const int r   = w >> 2;
            const int c   = w & 3;
            uint32_t dst = sbase + arr * 16384 + r * 64 + ((c ^ ((r >> 1) & 3)) << 4);
            const __nv_bfloat16* base = (arr == 0) ? aH : (arr == 1) ? aL : (arr == 2) ? bH : bL;
            cp_async16(dst, base + (size_t)r * DD + kt * 32 + c * 8);
        }
    };

    float acc[4][8][4];
    #pragma unroll
    for (int a = 0; a < 4; ++a)
        #pragma unroll
        for (int b = 0; b < 8; ++b)
            #pragma unroll
            for (int c = 0; c < 4; ++c) acc[a][b][c] = 0.f;

    // ldmatrix lane addressing (shared by A and B):
    // lane L: row_in_16 = (L&7) + 8*((L>>3)&1); k half sel = L>>4
    const int r_lane = (lane & 7) + ((lane >> 3) & 1) * 8;
    const int c_lane = lane >> 4;            // 0 or 1

    int rA64[4], rAx[4], rB64[4], rBx[4];
    #pragma unroll
    for (int f = 0; f < 4; ++f) {
        int ra = wm * 64 + f * 16 + r_lane;
        rA64[f] = ra * 64; rAx[f] = (ra >> 1) & 3;
        int rbn = wn * 64 + f * 16 + r_lane;
        rB64[f] = rbn * 64; rBx[f] = (rbn >> 1) & 3;
    }

    issue_stage(0, 0); CP_COMMIT();
    issue_stage(1, 1); CP_COMMIT();

    const int KT = DD / 32;                  // 256
    for (int kt = 0; kt < KT; ++kt) {
        CP_WAIT1();
        __syncthreads();

        const uint32_t sbase = sb + (kt % NSTG) * STAGE_BYTES;
        #pragma unroll
        for (int ks = 0; ks < 2; ++ks) {
            const int cbase = 2 * ks + c_lane;
            uint32_t a_hi[4][4], a_lo[4][4];
            #pragma unroll
            for (int mf = 0; mf < 4; ++mf) {
                uint32_t off = rA64[mf] + ((cbase ^ rAx[mf]) << 4);
                ldsm4(a_hi[mf], sbase + off);               // Ah at +0
                ldsm4(a_lo[mf], sbase + 16384 + off);       // Al
            }
            #pragma unroll
            for (int nf2 = 0; nf2 < 4; ++nf2) {
                uint32_t off = rB64[nf2] + ((cbase ^ rBx[nf2]) << 4);
                uint32_t b_hi[4], b_lo[4];
                ldsm4(b_hi, sbase + 32768 + off);           // Bh
                ldsm4(b_lo, sbase + 49152 + off);           // Bl
                #pragma unroll
                for (int mf = 0; mf < 4; ++mf) {
                    #pragma unroll
                    for (int s = 0; s < 2; ++s) {
                        float* d = acc[mf][nf2 * 2 + s];
                        mma16816(d, a_hi[mf], b_hi[s], b_hi[s + 2]);
                        mma16816(d, a_hi[mf], b_lo[s], b_lo[s + 2]);
                        mma16816(d, a_lo[mf], b_hi[s], b_hi[s + 2]);
                    }
                }
            }
        }
        __syncthreads();
        if (kt + 2 < KT) issue_stage(kt + 2, (kt + 2) % NSTG);
        CP_COMMIT();
    }

    // ---- epilogue: out = acc + rs[m]*b3[g], direct coalesced-enough STG ----
    const int r_ep  = lane >> 2;             // 0..7
    const int cpair = (lane & 3) * 2;

    float rsv[4][2];
    #pragma unroll
    for (int mf = 0; mf < 4; ++mf) {
        int row = rb * 256 + wm * 64 + mf * 16 + r_ep;
        rsv[mf][0] = g_rs[row];
        rsv[mf][1] = g_rs[row + 8];
    }
    float b3v[8][2];
    #pragma unroll
    for (int nf = 0; nf < 8; ++nf) {
        int colg = nb * 256 + wn * 64 + nf * 8 + cpair;
        b3v[nf][0] = b3[colg];
        b3v[nf][1] = b3[colg + 1];
    }

    #pragma unroll
    for (int mf = 0; mf < 4; ++mf) {
        #pragma unroll
        for (int nf = 0; nf < 8; ++nf) {
            int row = rb * 256 + wm * 64 + mf * 16 + r_ep;
            int colg = nb * 256 + wn * 64 + nf * 8 + cpair;
            float2 v0, v1;
            v0.x = acc[mf][nf][0] + rsv[mf][0] * b3v[nf][0];
            v0.y = acc[mf][nf][1] + rsv[mf][0] * b3v[nf][1];
            v1.x = acc[mf][nf][2] + rsv[mf][1] * b3v[nf][0];
            v1.y = acc[mf][nf][3] + rsv[mf][1] * b3v[nf][1];
            *(float2*)&out[(size_t)row * GG + colg]       = v0;
            *(float2*)&out[(size_t)(row + 8) * GG + colg] = v1;
        }
    }
}

// =============================================================================
extern "C" void kernel_launch(void* const* d_in, const int* in_sizes, int n_in,
                              void* d_out, int out_size)
{
    const float* x1 = (const float*)d_in[0];
    const float* x2 = (const float*)d_in[1];
    const float* w1 = (const float*)d_in[2];
    const float* b1 = (const float*)d_in[3];
    const float* w2 = (const float*)d_in[4];
    const float* b2 = (const float*)d_in[5];
    const float* w3 = (const float*)d_in[6];
    const float* b3 = (const float*)d_in[7];
    float* out = (float*)d_out;

    cudaFuncSetAttribute(k_out_tc, cudaFuncAttributeMaxDynamicSharedMemorySize, SMEM_K4);

    k_split_w3<<<(size_t)GG * DD / (256 * 4), 256>>>(w3);
    k_qk<<<MM / 16, 256>>>(x1, x2, w1, b1, w2, b2);
    k_scores_softmax<<<BB, 128>>>();
    k_y<<<dim3(DD / 512, TT / 64, BB), 512>>>(x1);
    k_out_tc<<<dim3(MM / 256, GG / 256), 512, SMEM_K4>>>(b3, out);
}

// round 7
// speedup vs baseline: 2.2563x; 1.3254x over previous
#include <cuda_runtime.h>
#include <cuda_bf16.h>
#include <stdint.h>
#include <math.h>

// Problem constants
#define BB 16
#define TT 128
#define DD 8192           // C*H*W
#define FF 16             // NUM_FEAT
#define GG 4096           // NUM_FEAT*H*W
#define MM (BB*TT)        // 2048 rows

// ---------------- scratch (device globals; no allocs allowed) ----------------
__device__ float g_q[MM * FF];
__device__ float g_k[MM * FF];
__device__ float g_attn[BB * TT * TT];
__device__ float g_rs[MM];
__device__ __nv_bfloat16 g_yhi[(size_t)MM * DD];   // 32 MB, row-major [m][k]
__device__ __nv_bfloat16 g_ylo[(size_t)MM * DD];   // 32 MB
__device__ __nv_bfloat16 g_w3hi[(size_t)GG * DD];  // 64 MB, row-major [n][k]
__device__ __nv_bfloat16 g_w3lo[(size_t)GG * DD];  // 64 MB

// ======================= PTX helpers (compute_103-safe) ======================
__device__ __forceinline__ uint32_t smem_u32(const void* p) {
    uint32_t a;
    asm("{ .reg .u64 t; cvta.to.shared.u64 t, %1; cvt.u32.u64 %0, t; }" : "=r"(a) : "l"(p));
    return a;
}
__device__ __forceinline__ void cp_async16(uint32_t dst, const void* src) {
    asm volatile("cp.async.cg.shared.global [%0], [%1], 16;" :: "r"(dst), "l"(src) : "memory");
}
#define CP_COMMIT() asm volatile("cp.async.commit_group;" ::: "memory")
#define CP_WAIT1()  asm volatile("cp.async.wait_group 1;" ::: "memory")

__device__ __forceinline__ void ldsm4(uint32_t* r, uint32_t addr) {
    asm volatile("ldmatrix.sync.aligned.m8n8.x4.shared.b16 {%0,%1,%2,%3}, [%4];"
        : "=r"(r[0]), "=r"(r[1]), "=r"(r[2]), "=r"(r[3]) : "r"(addr));
}
__device__ __forceinline__ void mma16816(float* d, const uint32_t* a, uint32_t b0, uint32_t b1) {
    asm volatile("mma.sync.aligned.m16n8k16.row.col.f32.bf16.bf16.f32 "
        "{%0,%1,%2,%3}, {%4,%5,%6,%7}, {%8,%9}, {%0,%1,%2,%3};"
        : "+f"(d[0]), "+f"(d[1]), "+f"(d[2]), "+f"(d[3])
        : "r"(a[0]), "r"(a[1]), "r"(a[2]), "r"(a[3]), "r"(b0), "r"(b1));
}

// =============================================================================
// K1: q = x1 @ w1^T + b1 ; k = x2 @ w2^T + b2
// (pad 132: row stride 528 B stays 16B-aligned for the float4 stores)
// =============================================================================
__global__ __launch_bounds__(256) void k_qk(
    const float* __restrict__ x1, const float* __restrict__ x2,
    const float* __restrict__ w1, const float* __restrict__ b1,
    const float* __restrict__ w2, const float* __restrict__ b2)
{
    __shared__ float Xs1[16][132];
    __shared__ float Xs2[16][132];
    __shared__ float Ws1[16][132];
    __shared__ float Ws2[16][132];

    const int tid  = threadIdx.x;
    const int r    = tid >> 4;
    const int f    = tid & 15;
    const int row0 = blockIdx.x * 16;

    float accq = 0.f, acck = 0.f;
    for (int kc = 0; kc < DD; kc += 128) {
        #pragma unroll
        for (int i = 0; i < 2; ++i) {
            int lin = tid + i * 256;
            int row = lin >> 5;
            int col = (lin & 31) << 2;
            *(float4*)&Xs1[row][col] = *(const float4*)&x1[(size_t)(row0 + row) * DD + kc + col];
            *(float4*)&Xs2[row][col] = *(const float4*)&x2[(size_t)(row0 + row) * DD + kc + col];
            *(float4*)&Ws1[row][col] = *(const float4*)&w1[(size_t)row * DD + kc + col];
            *(float4*)&Ws2[row][col] = *(const float4*)&w2[(size_t)row * DD + kc + col];
        }
        __syncthreads();
        #pragma unroll 8
        for (int kk = 0; kk < 128; ++kk) {
            accq += Xs1[r][kk] * Ws1[f][kk];
            acck += Xs2[r][kk] * Ws2[f][kk];
        }
        __syncthreads();
    }
    g_q[(row0 + r) * FF + f] = accq + b1[f];
    g_k[(row0 + r) * FF + f] = acck + b2[f];
}

// =============================================================================
// K2: scores + softmax over t (axis=1) + rowsums
// =============================================================================
__global__ __launch_bounds__(128) void k_scores_softmax()
{
    __shared__ float qs[TT][17];
    __shared__ float redp[4][TT];

    const int b = blockIdx.x;
    const int s = threadIdx.x;
    const int lane = s & 31, wid = s >> 5;

    #pragma unroll
    for (int i = 0; i < 16; ++i) {
        int lin = s + i * 128;
        int t = lin >> 4, f = lin & 15;
        qs[t][f] = g_q[(b * TT + t) * FF + f];
    }
    float kr[FF];
    #pragma unroll
    for (int j = 0; j < FF; ++j) kr[j] = g_k[(b * TT + s) * FF + j];
    __syncthreads();

    float m = -1e30f, l = 0.f;
    for (int t = 0; t < TT; ++t) {
        float sc = 0.f;
        #pragma unroll
        for (int j = 0; j < FF; ++j) sc += qs[t][j] * kr[j];
        float nm = fmaxf(m, sc);
        l = l * expf(m - nm) + expf(sc - nm);
        m = nm;
    }
    float inv = 1.f / l;

    for (int t = 0; t < TT; ++t) {
        float sc = 0.f;
        #pragma unroll
        for (int j = 0; j < FF; ++j) sc += qs[t][j] * kr[j];
        float a = expf(sc - m) * inv;
        g_attn[(b * TT + t) * TT + s] = a;

        float v = a;
        #pragma unroll
        for (int off = 16; off > 0; off >>= 1)
            v += __shfl_down_sync(0xffffffffu, v, off);
        if (lane == 0) redp[wid][t] = v;
    }
    __syncthreads();
    if (s < TT)
        g_rs[b * TT + s] = redp[0][s] + redp[1][s] + redp[2][s] + redp[3][s];
}

// =============================================================================
// K3: y[b,t,d] = sum_s attn[b,t,s] * x1[b,s,d] -> bf16 hi/lo. s unrolled x4
// (4 batched LDGs -> MLP 4 to hide L2 latency under the 256 FFMAs).
// =============================================================================
__global__ __launch_bounds__(512) void k_y(const float* __restrict__ x1)
{
    __shared__ float AsT[TT][68];

    const int tid = threadIdx.x;
    const int b   = blockIdx.z;
    const int t0  = blockIdx.y * 64;
    const int col = blockIdx.x * 512 + tid;

    #pragma unroll
    for (int i = 0; i < 16; ++i) {
        int lin = tid + i * 512;
        int s = lin & 127, t = lin >> 7;
        AsT[s][t] = g_attn[(b * TT + t0 + t) * TT + s];
    }
    __syncthreads();

    float acc[64];
    #pragma unroll
    for (int t = 0; t < 64; ++t) acc[t] = 0.f;

    const float* xp = x1 + (size_t)b * TT * DD + col;
    for (int s = 0; s < TT; s += 4) {
        float xv0 = xp[(size_t)(s + 0) * DD];
        float xv1 = xp[(size_t)(s + 1) * DD];
        float xv2 = xp[(size_t)(s + 2) * DD];
        float xv3 = xp[(size_t)(s + 3) * DD];
        #pragma unroll
        for (int u = 0; u < 4; ++u) {
            float xv = (u == 0) ? xv0 : (u == 1) ? xv1 : (u == 2) ? xv2 : xv3;
            const float4* ar = (const float4*)&AsT[s + u][0];
            #pragma unroll
            for (int q4 = 0; q4 < 16; ++q4) {
                float4 a = ar[q4];
                acc[q4 * 4 + 0] += a.x * xv;
                acc[q4 * 4 + 1] += a.y * xv;
                acc[q4 * 4 + 2] += a.z * xv;
                acc[q4 * 4 + 3] += a.w * xv;
            }
        }
    }
    #pragma unroll
    for (int t = 0; t < 64; ++t) {
        float v = acc[t];
        __nv_bfloat16 h = __float2bfloat16(v);
        __nv_bfloat16 lo = __float2bfloat16(v - __bfloat162float(h));
        size_t off = (size_t)(b * TT + t0 + t) * DD + col;
        g_yhi[off] = h;
        g_ylo[off] = lo;
    }
}

// =============================================================================
// K_split_w3: fp32 [G][D] -> bf16 hi/lo row-major (streaming)
// =============================================================================
__global__ __launch_bounds__(256) void k_split_w3(const float* __restrict__ src)
{
    size_t i4 = ((size_t)blockIdx.x * 256 + threadIdx.x);
    float4 v = *(const float4*)&src[i4 * 4];
    __nv_bfloat16 h0 = __float2bfloat16(v.x), h1 = __float2bfloat16(v.y);
    __nv_bfloat16 h2 = __float2bfloat16(v.z), h3 = __float2bfloat16(v.w);
    __nv_bfloat162 hp0; hp0.x = h0; hp0.y = h1;
    __nv_bfloat162 hp1; hp1.x = h2; hp1.y = h3;
    __nv_bfloat162 lp0, lp1;
    lp0.x = __float2bfloat16(v.x - __bfloat162float(h0));
    lp0.y = __float2bfloat16(v.y - __bfloat162float(h1));
    lp1.x = __float2bfloat16(v.z - __bfloat162float(h2));
    lp1.y = __float2bfloat16(v.w - __bfloat162float(h3));
    uint2 hu, lu;
    hu.x = *(uint32_t*)&hp0; hu.y = *(uint32_t*)&hp1;
    lu.x = *(uint32_t*)&lp0; lu.y = *(uint32_t*)&lp1;
    *(uint2*)&g_w3hi[i4 * 4] = hu;
    *(uint2*)&g_w3lo[i4 * 4] = lu;
}

// =============================================================================
// K4: out[m,g] = sum_k y[m,k] w3[g,k] + rs[m] b3[g]
// bf16 hi/lo 3-product HMMA. Block tile 256x128, BK=32, 512 threads,
// 16 warps as 4m x 4n, warp tile 64x32 -> acc=64 regs (no spills at 128 cap).
// Stage: Ah 16K | Al 16K | Bh 8K | Bl 8K = 48KB, 3 stages = 144KB.
// Smem rows 64B, chunk swizzle c ^= (r>>1)&3 (ldsm + cp.async conflict-free).
// =============================================================================
#define STAGE_BYTES 49152
#define NSTG 3
#define SMEM_K4 (NSTG * STAGE_BYTES)
#define OFF_AL 16384
#define OFF_BH 32768
#define OFF_BL 40960

__global__ __launch_bounds__(512) void k_out_tc(
    const float* __restrict__ b3, float* __restrict__ out)
{
    extern __shared__ char smem[];
    const uint32_t sb = smem_u32(smem);
    const int tid  = threadIdx.x;
    const int lane = tid & 31;
    const int wid  = tid >> 5;
    const int wm   = wid & 3;          // warp m index (0..3), 64 rows each
    const int wn   = wid >> 2;         // warp n index (0..3), 32 cols each
    const int rb   = blockIdx.x;       // M tile (0..7)   -> 256 rows
    const int nb   = blockIdx.y;       // N tile (0..31)  -> 128 cols

    const __nv_bfloat16* aH = g_yhi  + (size_t)rb * 256 * DD;
    const __nv_bfloat16* aL = g_ylo  + (size_t)rb * 256 * DD;
    const __nv_bfloat16* bH = g_w3hi + (size_t)nb * 128 * DD;
    const __nv_bfloat16* bL = g_w3lo + (size_t)nb * 128 * DD;

    // loader: 6 x 16B chunks per thread per stage (A: 4, B: 2)
    auto issue_stage = [&](int kt, int stage) {
        const uint32_t sbase = sb + stage * STAGE_BYTES;
        #pragma unroll
        for (int i = 0; i < 4; ++i) {                 // A hi/lo: 2048 chunks
            const int id  = i * 512 + tid;
            const int arr = id >> 10;                 // 0=Ah 1=Al
            const int w   = id & 1023;
            const int r   = w >> 2;                   // 0..255
            const int c   = w & 3;
            uint32_t dst = sbase + arr * OFF_AL + r * 64 + ((c ^ ((r >> 1) & 3)) << 4);
            const __nv_bfloat16* base = arr ? aL : aH;
            cp_async16(dst, base + (size_t)r * DD + kt * 32 + c * 8);
        }
        #pragma unroll
        for (int i = 0; i < 2; ++i) {                 // B hi/lo: 1024 chunks
            const int id  = i * 512 + tid;
            const int arr = id >> 9;                  // 0=Bh 1=Bl
            const int w   = id & 511;
            const int r   = w >> 2;                   // 0..127
            const int c   = w & 3;
            uint32_t dst = sbase + OFF_BH + arr * 8192 + r * 64 + ((c ^ ((r >> 1) & 3)) << 4);
            const __nv_bfloat16* base = arr ? bL : bH;
            cp_async16(dst, base + (size_t)r * DD + kt * 32 + c * 8);
        }
    };

    float acc[4][4][4];                               // [mf][n8][frag]
    #pragma unroll
    for (int a = 0; a < 4; ++a)
        #pragma unroll
        for (int b = 0; b < 4; ++b)
            #pragma unroll
            for (int c = 0; c < 4; ++c) acc[a][b][c] = 0.f;

    const int r_lane = (lane & 7) + ((lane >> 3) & 1) * 8;
    const int c_lane = lane >> 4;                     // 0 or 1

    int rA64[4], rAx[4], rB64[2], rBx[2];
    #pragma unroll
    for (int f = 0; f < 4; ++f) {
        int ra = wm * 64 + f * 16 + r_lane;
        rA64[f] = ra * 64; rAx[f] = (ra >> 1) & 3;
    }
    #pragma unroll
    for (int f = 0; f < 2; ++f) {
        int rn = wn * 32 + f * 16 + r_lane;
        rB64[f] = rn * 64; rBx[f] = (rn >> 1) & 3;
    }

    issue_stage(0, 0); CP_COMMIT();
    issue_stage(1, 1); CP_COMMIT();

    const int KT = DD / 32;                           // 256
    for (int kt = 0; kt < KT; ++kt) {
        CP_WAIT1();
        __syncthreads();

        const uint32_t sbase = sb + (kt % NSTG) * STAGE_BYTES;
        #pragma unroll
        for (int ks = 0; ks < 2; ++ks) {
            const int cbase = 2 * ks + c_lane;
            uint32_t a_hi[4][4], a_lo[4][4];
            #pragma unroll
            for (int mf = 0; mf < 4; ++mf) {
                uint32_t off = rA64[mf] + ((cbase ^ rAx[mf]) << 4);
                ldsm4(a_hi[mf], sbase + off);
                ldsm4(a_lo[mf], sbase + OFF_AL + off);
            }
            #pragma unroll
            for (int nf2 = 0; nf2 < 2; ++nf2) {
                uint32_t off = rB64[nf2] + ((cbase ^ rBx[nf2]) << 4);
                uint32_t b_hi[4], b_lo[4];
                ldsm4(b_hi, sbase + OFF_BH + off);
                ldsm4(b_lo, sbase + OFF_BL + off);
                #pragma unroll
                for (int mf = 0; mf < 4; ++mf) {
                    #pragma unroll
                    for (int s = 0; s < 2; ++s) {
                        float* d = acc[mf][nf2 * 2 + s];
                        mma16816(d, a_hi[mf], b_hi[s], b_hi[s + 2]);
                        mma16816(d, a_hi[mf], b_lo[s], b_lo[s + 2]);
                        mma16816(d, a_lo[mf], b_hi[s], b_hi[s + 2]);
                    }
                }
            }
        }
        __syncthreads();
        if (kt + 2 < KT) issue_stage(kt + 2, (kt + 2) % NSTG);
        CP_COMMIT();
    }

    // ---- epilogue: out = acc + rs[m]*b3[g] ----
    const int r_ep  = lane >> 2;
    const int cpair = (lane & 3) * 2;

    float rsv[4][2];
    #pragma unroll
    for (int mf = 0; mf < 4; ++mf) {
        int row = rb * 256 + wm * 64 + mf * 16 + r_ep;
        rsv[mf][0] = g_rs[row];
        rsv[mf][1] = g_rs[row + 8];
    }
    float b3v[4][2];
    #pragma unroll
    for (int nf = 0; nf < 4; ++nf) {
        int colg = nb * 128 + wn * 32 + nf * 8 + cpair;
        b3v[nf][0] = b3[colg];
        b3v[nf][1] = b3[colg + 1];
    }

    #pragma unroll
    for (int mf = 0; mf < 4; ++mf) {
        #pragma unroll
        for (int nf = 0; nf < 4; ++nf) {
            int row  = rb * 256 + wm * 64 + mf * 16 + r_ep;
            int colg = nb * 128 + wn * 32 + nf * 8 + cpair;
            float2 v0, v1;
            v0.x = acc[mf][nf][0] + rsv[mf][0] * b3v[nf][0];
            v0.y = acc[mf][nf][1] + rsv[mf][0] * b3v[nf][1];
            v1.x = acc[mf][nf][2] + rsv[mf][1] * b3v[nf][0];
            v1.y = acc[mf][nf][3] + rsv[mf][1] * b3v[nf][1];
            *(float2*)&out[(size_t)row * GG + colg]       = v0;
            *(float2*)&out[(size_t)(row + 8) * GG + colg] = v1;
        }
    }
}

// =============================================================================
extern "C" void kernel_launch(void* const* d_in, const int* in_sizes, int n_in,
                              void* d_out, int out_size)
{
    const float* x1 = (const float*)d_in[0];
    const float* x2 = (const float*)d_in[1];
    const float* w1 = (const float*)d_in[2];
    const float* b1 = (const float*)d_in[3];
    const float* w2 = (const float*)d_in[4];
    const float* b2 = (const float*)d_in[5];
    const float* w3 = (const float*)d_in[6];
    const float* b3 = (const float*)d_in[7];
    float* out = (float*)d_out;

    cudaFuncSetAttribute(k_out_tc, cudaFuncAttributeMaxDynamicSharedMemorySize, SMEM_K4);

    k_split_w3<<<(size_t)GG * DD / (256 * 4), 256>>>(w3);
    k_qk<<<MM / 16, 256>>>(x1, x2, w1, b1, w2, b2);
    k_scores_softmax<<<BB, 128>>>();
    k_y<<<dim3(DD / 512, TT / 64, BB), 512>>>(x1);
    k_out_tc<<<dim3(MM / 256, GG / 128), 512, SMEM_K4>>>(b3, out);
}